// round 6
// baseline (speedup 1.0000x reference)
#include <cuda_runtime.h>
#include <cstdint>
#include <cmath>

#define BSZ 2
#define PP 512
#define NN 2048
#define DD 768
#define HH 12
#define HD 64
#define ROWS 2560
#define MTOT 5120
#define QKV3 2304

// Scratch (__device__ globals: allocation-free rule)
__device__ float g_qkv [(size_t)MTOT * QKV3];   // qkv activations f32
__device__ float g_attn[(size_t)MTOT * DD];     // attention output f32
__device__ float g_ahi [(size_t)MTOT * DD];     // 3xTF32 split of GEMM A operand (reused)
__device__ float g_alo [(size_t)MTOT * DD];
__device__ float g_whi [(size_t)DD * QKV3];     // qkv_w split
__device__ float g_wlo [(size_t)DD * QKV3];
__device__ float g_pwhi[(size_t)DD * DD];       // proj_w split
__device__ float g_pwlo[(size_t)DD * DD];
__device__ float g_mbias[BSZ * ROWS];           // -inf where masked, 0 elsewhere (padded)

#define NEG_INF __int_as_float(0xff800000)

__device__ __forceinline__ uint32_t f2tf(float x) {
    uint32_t r; asm("cvt.rna.tf32.f32 %0, %1;" : "=r"(r) : "f"(x)); return r;
}
__device__ __forceinline__ void mma8(float4& d, const uint32_t* a, uint32_t b0, uint32_t b1) {
    asm volatile(
        "mma.sync.aligned.m16n8k8.row.col.f32.tf32.tf32.f32 "
        "{%0,%1,%2,%3},{%4,%5,%6,%7},{%8,%9},{%0,%1,%2,%3};"
        : "+f"(d.x), "+f"(d.y), "+f"(d.z), "+f"(d.w)
        : "r"(a[0]), "r"(a[1]), "r"(a[2]), "r"(a[3]), "r"(b0), "r"(b1));
}
__device__ __forceinline__ void tfsplit(float x, float& hi, float& lo) {
    hi = __uint_as_float(f2tf(x));
    lo = __uint_as_float(f2tf(x - hi));
}

// ---------------------------------------------------------------------------
// Mask: detect upload dtype (bool8 / int32 / float32) and build -inf/0 bias,
// zero-padded to 2560 per batch so attention never branches on kv index.
// ---------------------------------------------------------------------------
__global__ void mask_convert(const uint32_t* __restrict__ mw)
{
    __shared__ int is_bool;
    const int tid = threadIdx.x;
    if (tid == 0) is_bool = 0;
    __syncthreads();
    if (tid < 256) {
        uint32_t w = mw[tid];
        if (w > 1u && w != 0x3F800000u) atomicOr(&is_bool, 1);
    }
    __syncthreads();
    const int i = blockIdx.x * 1024 + tid;          // over BSZ*ROWS = 5120
    const int b = i / ROWS, p = i % ROWS;
    float v = 0.0f;
    if (p < PP) {
        const int mi = b * PP + p;
        bool m = is_bool ? (((const uint8_t*)mw)[mi] != 0) : (mw[mi] != 0u);
        v = m ? NEG_INF : 0.0f;
    }
    g_mbias[i] = v;
}

// ---------------------------------------------------------------------------
// Split activations (virtual concat [xq; xs]) into tf32 hi/lo
// ---------------------------------------------------------------------------
__global__ void split_act(const float* __restrict__ xs, const float* __restrict__ xq)
{
    const int i = blockIdx.x * 256 + threadIdx.x;   // over MTOT*DD/4
    const int row = i / (DD / 4), q = (i % (DD / 4)) * 4;
    const int b = row / ROWS, r = row % ROWS;
    const float* src = (r < NN) ? xq + ((size_t)b * NN + r) * DD
                                : xs + ((size_t)b * PP + (r - NN)) * DD;
    float4 v = *(const float4*)(src + q);
    float4 h, l;
    tfsplit(v.x, h.x, l.x); tfsplit(v.y, h.y, l.y);
    tfsplit(v.z, h.z, l.z); tfsplit(v.w, h.w, l.w);
    *(float4*)(g_ahi + (size_t)row * DD + q) = h;
    *(float4*)(g_alo + (size_t)row * DD + q) = l;
}

__global__ void split_mat(const float* __restrict__ src, float* __restrict__ dhi,
                          float* __restrict__ dlo)
{
    const int i = blockIdx.x * 256 + threadIdx.x;   // over n/4 float4s
    float4 v = *(const float4*)(src + (size_t)i * 4);
    float4 h, l;
    tfsplit(v.x, h.x, l.x); tfsplit(v.y, h.y, l.y);
    tfsplit(v.z, h.z, l.z); tfsplit(v.w, h.w, l.w);
    *(float4*)(dhi + (size_t)i * 4) = h;
    *(float4*)(dlo + (size_t)i * 4) = l;
}

__global__ void split_attn()
{
    const int i = blockIdx.x * 256 + threadIdx.x;   // over MTOT*DD/4
    float4 v = *(const float4*)(g_attn + (size_t)i * 4);
    float4 h, l;
    tfsplit(v.x, h.x, l.x); tfsplit(v.y, h.y, l.y);
    tfsplit(v.z, h.z, l.z); tfsplit(v.w, h.w, l.w);
    *(float4*)(g_ahi + (size_t)i * 4) = h;
    *(float4*)(g_alo + (size_t)i * 4) = l;
}

// ---------------------------------------------------------------------------
// 3xTF32 GEMM: C[M x NB] = A[M x 768] @ B[768 x NB] + bias
// EPI 0: C -> g_qkv (NB=2304).  EPI 1: scatter to tuple output (NB=768).
// 128x128 tile, BK=32, 8 warps (4x2), warp tile 32x64, m16n8k8 MMA.
// smem strides: A 36 (bank = 4*lg+lt, conflict-free), B 136 (bank = 8*lt+lg).
// ---------------------------------------------------------------------------
#define AST 36
#define BST 136
#define GEMM_SMEM ((128 * AST * 2 + 32 * BST * 2) * 4)

template <int EPI>
__global__ __launch_bounds__(256, 2) void gemm3x(
    const float* __restrict__ Bh_g, const float* __restrict__ Bl_g,
    const float* __restrict__ bias, float* __restrict__ Cout)
{
    constexpr int NB = (EPI == 0) ? QKV3 : DD;
    extern __shared__ float smf[];
    float* Ah = smf;
    float* Al = Ah + 128 * AST;
    float* Bh = Al + 128 * AST;
    float* Bl = Bh + 32 * BST;

    const int tid = threadIdx.x;
    const int bx = blockIdx.x, by = blockIdx.y;
    const int wid = tid >> 5, lane = tid & 31;
    const int wm = wid >> 1, wn = wid & 1;
    const int lg = lane >> 2, lt = lane & 3;
    const int row0 = by * 128, col0 = bx * 128;

    float4 acc[2][8];
#pragma unroll
    for (int mi = 0; mi < 2; mi++)
#pragma unroll
        for (int ni = 0; ni < 8; ni++) acc[mi][ni] = make_float4(0.f, 0.f, 0.f, 0.f);

    for (int k0 = 0; k0 < DD; k0 += 32) {
        __syncthreads();
#pragma unroll
        for (int i = 0; i < 4; i++) {
            const int id = tid + i * 256;
            const int r = id >> 3, q = (id & 7) * 4;
            const size_t go = (size_t)(row0 + r) * DD + k0 + q;
            *(float4*)(Ah + r * AST + q) = *(const float4*)(g_ahi + go);
            *(float4*)(Al + r * AST + q) = *(const float4*)(g_alo + go);
        }
#pragma unroll
        for (int i = 0; i < 4; i++) {
            const int id = tid + i * 256;
            const int r = id >> 5, q = (id & 31) * 4;
            const size_t go = (size_t)(k0 + r) * NB + col0 + q;
            *(float4*)(Bh + r * BST + q) = *(const float4*)(Bh_g + go);
            *(float4*)(Bl + r * BST + q) = *(const float4*)(Bl_g + go);
        }
        __syncthreads();

#pragma unroll
        for (int ks = 0; ks < 4; ks++) {
            uint32_t ah[2][4], al[2][4];
            const int c = ks * 8 + lt;
#pragma unroll
            for (int mi = 0; mi < 2; mi++) {
                const int rb = wm * 32 + mi * 16;
                ah[mi][0] = __float_as_uint(Ah[(rb + lg) * AST + c]);
                ah[mi][1] = __float_as_uint(Ah[(rb + 8 + lg) * AST + c]);
                ah[mi][2] = __float_as_uint(Ah[(rb + lg) * AST + c + 4]);
                ah[mi][3] = __float_as_uint(Ah[(rb + 8 + lg) * AST + c + 4]);
                al[mi][0] = __float_as_uint(Al[(rb + lg) * AST + c]);
                al[mi][1] = __float_as_uint(Al[(rb + 8 + lg) * AST + c]);
                al[mi][2] = __float_as_uint(Al[(rb + lg) * AST + c + 4]);
                al[mi][3] = __float_as_uint(Al[(rb + 8 + lg) * AST + c + 4]);
            }
#pragma unroll
            for (int ni = 0; ni < 8; ni++) {
                const int nb = wn * 64 + ni * 8 + lg;
                const uint32_t bh0 = __float_as_uint(Bh[c * BST + nb]);
                const uint32_t bh1 = __float_as_uint(Bh[(c + 4) * BST + nb]);
                const uint32_t bl0 = __float_as_uint(Bl[c * BST + nb]);
                const uint32_t bl1 = __float_as_uint(Bl[(c + 4) * BST + nb]);
#pragma unroll
                for (int mi = 0; mi < 2; mi++) {
                    mma8(acc[mi][ni], ah[mi], bh0, bh1);
                    mma8(acc[mi][ni], ah[mi], bl0, bl1);
                    mma8(acc[mi][ni], al[mi], bh0, bh1);
                }
            }
        }
    }

    // Epilogue
#pragma unroll
    for (int mi = 0; mi < 2; mi++) {
        const int r0 = row0 + wm * 32 + mi * 16 + lg;
#pragma unroll
        for (int ni = 0; ni < 8; ni++) {
            const int col = col0 + wn * 64 + ni * 8 + lt * 2;
            const float b0 = __ldg(&bias[col]), b1 = __ldg(&bias[col + 1]);
            float2 v0 = {acc[mi][ni].x + b0, acc[mi][ni].y + b1};
            float2 v1 = {acc[mi][ni].z + b0, acc[mi][ni].w + b1};
            if (EPI == 0) {
                *(float2*)(g_qkv + (size_t)r0 * NB + col) = v0;
                *(float2*)(g_qkv + (size_t)(r0 + 8) * NB + col) = v1;
            } else {
                // tuple scatter: rows <512 are xs, rest xq
#pragma unroll
                for (int rr = 0; rr < 2; rr++) {
                    const int g = r0 + rr * 8;
                    const int b = g / ROWS, r = g % ROWS;
                    float* dst = (r < PP)
                        ? Cout + ((size_t)b * PP + r) * DD
                        : Cout + (size_t)BSZ * PP * DD + ((size_t)b * NN + (r - PP)) * DD;
                    *(float2*)(dst + col) = rr ? v1 : v0;
                }
            }
        }
    }
}

// ---------------------------------------------------------------------------
// TF32 flash attention. BQ=128 (8 warps x m16), BKV=64, d=64.
// Q frags in registers; K (stride 68) / V (stride 72) in smem, conflict-free.
// Online softmax with quad shuffles; P C-layout -> A-layout via 8 shfl/group.
// ---------------------------------------------------------------------------
#define KST 68
#define VST 72
#define ATTN_SMEM ((64 * KST + 64 * VST + 64) * 4)   // Q tile (128*68) fits in same region

__global__ __launch_bounds__(256) void attn_tc(int q_start, int Lk, int self_mode)
{
    extern __shared__ float smf[];
    float* Qs = smf;                 // [128][68] (temporarily)
    float* Ks = smf;                 // [64][68]
    float* Vs = smf + 64 * KST;      // [64][72]
    float* msk = smf + 64 * KST + 64 * VST;  // [64]

    const int tid = threadIdx.x, wid = tid >> 5, lane = tid & 31;
    const int lg = lane >> 2, lt = lane & 3;
    const int h = blockIdx.y, b = blockIdx.z;
    const int q0 = blockIdx.x * 128;
    const size_t rowbase = (size_t)b * ROWS;

    // Stage Q (tf32) and pull fragments into registers
    const float* qg = g_qkv + (rowbase + q_start + q0) * QKV3 + h * HD;
#pragma unroll
    for (int i = 0; i < 8; i++) {
        const int id = tid + i * 256;
        const int r = id >> 4, q = (id & 15) * 4;
        float4 v = *(const float4*)(qg + (size_t)r * QKV3 + q);
        uint4 t = {f2tf(v.x), f2tf(v.y), f2tf(v.z), f2tf(v.w)};
        *(uint4*)(Qs + r * KST + q) = t;
    }
    __syncthreads();
    uint32_t qf[8][4];
    {
        const int rb = wid * 16;
#pragma unroll
        for (int kf = 0; kf < 8; kf++) {
            const int c = kf * 8 + lt;
            qf[kf][0] = __float_as_uint(Qs[(rb + lg) * KST + c]);
            qf[kf][1] = __float_as_uint(Qs[(rb + 8 + lg) * KST + c]);
            qf[kf][2] = __float_as_uint(Qs[(rb + lg) * KST + c + 4]);
            qf[kf][3] = __float_as_uint(Qs[(rb + 8 + lg) * KST + c + 4]);
        }
    }

    float4 oacc[8];
#pragma unroll
    for (int d = 0; d < 8; d++) oacc[d] = make_float4(0.f, 0.f, 0.f, 0.f);
    float m0 = NEG_INF, m1 = NEG_INF, l0 = 0.f, l1 = 0.f;

    for (int kv0 = 0; kv0 < Lk; kv0 += 64) {
        __syncthreads();
        const float* kg = g_qkv + (rowbase + kv0) * QKV3 + DD + h * HD;
        const float* vg = kg + DD;
#pragma unroll
        for (int i = 0; i < 4; i++) {
            const int id = tid + i * 256;
            const int r = id >> 4, q = (id & 15) * 4;
            float4 v = *(const float4*)(kg + (size_t)r * QKV3 + q);
            uint4 t = {f2tf(v.x), f2tf(v.y), f2tf(v.z), f2tf(v.w)};
            *(uint4*)(Ks + r * KST + q) = t;
            float4 v2 = *(const float4*)(vg + (size_t)r * QKV3 + q);
            uint4 t2 = {f2tf(v2.x), f2tf(v2.y), f2tf(v2.z), f2tf(v2.w)};
            *(uint4*)(Vs + r * VST + q) = t2;
        }
        if (tid < 64) msk[tid] = g_mbias[b * ROWS + kv0 + tid];
        __syncthreads();

        // S = Q @ K^T
        float4 sacc[8];
#pragma unroll
        for (int ni = 0; ni < 8; ni++) sacc[ni] = make_float4(0.f, 0.f, 0.f, 0.f);
#pragma unroll
        for (int kf = 0; kf < 8; kf++) {
            const int c = kf * 8 + lt;
#pragma unroll
            for (int ni = 0; ni < 8; ni++) {
                const int n = ni * 8 + lg;
                mma8(sacc[ni], qf[kf],
                     __float_as_uint(Ks[n * KST + c]),
                     __float_as_uint(Ks[n * KST + c + 4]));
            }
        }

        // scale + mask bias, row max
        float rmax0 = NEG_INF, rmax1 = NEG_INF;
#pragma unroll
        for (int ni = 0; ni < 8; ni++) {
            const float mb0 = msk[ni * 8 + lt * 2];
            const float mb1 = msk[ni * 8 + lt * 2 + 1];
            sacc[ni].x = sacc[ni].x * 0.125f + mb0;
            sacc[ni].y = sacc[ni].y * 0.125f + mb1;
            sacc[ni].z = sacc[ni].z * 0.125f + mb0;
            sacc[ni].w = sacc[ni].w * 0.125f + mb1;
            rmax0 = fmaxf(rmax0, fmaxf(sacc[ni].x, sacc[ni].y));
            rmax1 = fmaxf(rmax1, fmaxf(sacc[ni].z, sacc[ni].w));
        }
        rmax0 = fmaxf(rmax0, __shfl_xor_sync(0xffffffffu, rmax0, 1));
        rmax0 = fmaxf(rmax0, __shfl_xor_sync(0xffffffffu, rmax0, 2));
        rmax1 = fmaxf(rmax1, __shfl_xor_sync(0xffffffffu, rmax1, 1));
        rmax1 = fmaxf(rmax1, __shfl_xor_sync(0xffffffffu, rmax1, 2));

        const float nm0 = fmaxf(m0, rmax0), nm1 = fmaxf(m1, rmax1);
        const float s0 = (nm0 == NEG_INF) ? 0.f : nm0;
        const float s1 = (nm1 == NEG_INF) ? 0.f : nm1;
        const float f0 = __expf(m0 - s0), f1 = __expf(m1 - s1);
        m0 = nm0; m1 = nm1;

        float rs0 = 0.f, rs1 = 0.f;
#pragma unroll
        for (int ni = 0; ni < 8; ni++) {
            sacc[ni].x = __expf(sacc[ni].x - s0);
            sacc[ni].y = __expf(sacc[ni].y - s0);
            sacc[ni].z = __expf(sacc[ni].z - s1);
            sacc[ni].w = __expf(sacc[ni].w - s1);
            rs0 += sacc[ni].x + sacc[ni].y;
            rs1 += sacc[ni].z + sacc[ni].w;
        }
        rs0 += __shfl_xor_sync(0xffffffffu, rs0, 1);
        rs0 += __shfl_xor_sync(0xffffffffu, rs0, 2);
        rs1 += __shfl_xor_sync(0xffffffffu, rs1, 1);
        rs1 += __shfl_xor_sync(0xffffffffu, rs1, 2);
        l0 = l0 * f0 + rs0;
        l1 = l1 * f1 + rs1;
#pragma unroll
        for (int d = 0; d < 8; d++) {
            oacc[d].x *= f0; oacc[d].y *= f0;
            oacc[d].z *= f1; oacc[d].w *= f1;
        }

        // P (C-layout) -> A-frags via shuffles, then O += P @ V
        const int src1 = (lane & ~3) | (lt >> 1);
        const int src2 = src1 + 2;
        const bool odd = lane & 1;
#pragma unroll
        for (int g = 0; g < 8; g++) {
            const float v0 = __shfl_sync(0xffffffffu, sacc[g].x, src1);
            const float v1 = __shfl_sync(0xffffffffu, sacc[g].y, src1);
            const float v2 = __shfl_sync(0xffffffffu, sacc[g].z, src1);
            const float v3 = __shfl_sync(0xffffffffu, sacc[g].w, src1);
            const float w0 = __shfl_sync(0xffffffffu, sacc[g].x, src2);
            const float w1 = __shfl_sync(0xffffffffu, sacc[g].y, src2);
            const float w2 = __shfl_sync(0xffffffffu, sacc[g].z, src2);
            const float w3 = __shfl_sync(0xffffffffu, sacc[g].w, src2);
            uint32_t pa[4];
            pa[0] = f2tf(odd ? v1 : v0);
            pa[1] = f2tf(odd ? v3 : v2);
            pa[2] = f2tf(odd ? w1 : w0);
            pa[3] = f2tf(odd ? w3 : w2);
            const int kr0 = (g * 8 + lt) * VST;
            const int kr1 = (g * 8 + lt + 4) * VST;
#pragma unroll
            for (int d = 0; d < 8; d++) {
                const int dc = d * 8 + lg;
                mma8(oacc[d], pa,
                     __float_as_uint(Vs[kr0 + dc]),
                     __float_as_uint(Vs[kr1 + dc]));
            }
        }
    }

    // Finalize
    const float inv0 = 1.f / l0, inv1 = 1.f / l1;
    if (!self_mode) {
        const int r0 = q_start + q0 + wid * 16 + lg;
#pragma unroll
        for (int d = 0; d < 8; d++) {
            const int col = h * HD + d * 8 + lt * 2;
            float2 a = {oacc[d].x * inv0, oacc[d].y * inv0};
            float2 c = {oacc[d].z * inv1, oacc[d].w * inv1};
            *(float2*)(g_attn + (rowbase + r0) * DD + col) = a;
            *(float2*)(g_attn + (rowbase + r0 + 8) * DD + col) = c;
        }
    } else {
        const int p0 = q0 + wid * 16 + lg, p1 = p0 + 8;
#pragma unroll
        for (int d = 0; d < 8; d++) {
            const int k = d * 8 + lt * 2;
#pragma unroll
            for (int e = 0; e < 4; e++) {
                const int kk = k + (e & 1);
                const int pp = (e < 2) ? p0 : p1;
                const float val = ((e == 0) ? oacc[d].x * inv0 :
                                   (e == 1) ? oacc[d].y * inv0 :
                                   (e == 2) ? oacc[d].z * inv1 : oacc[d].w * inv1);
                const int f = (h * HD + kk) * PP + pp;
                g_attn[(rowbase + f / DD) * DD + (f % DD)] = val;
            }
        }
    }
}

// ---------------------------------------------------------------------------
extern "C" void kernel_launch(void* const* d_in, const int* in_sizes, int n_in,
                              void* d_out, int out_size)
{
    const float*    xs     = (const float*)d_in[0];
    const float*    xq     = (const float*)d_in[1];
    const uint32_t* mask   = (const uint32_t*)d_in[2];
    const float*    qkv_w  = (const float*)d_in[3];
    const float*    qkv_b  = (const float*)d_in[4];
    const float*    proj_w = (const float*)d_in[5];
    const float*    proj_b = (const float*)d_in[6];
    float*          out    = (float*)d_out;
    (void)in_sizes; (void)n_in; (void)out_size;

    cudaFuncSetAttribute(gemm3x<0>, cudaFuncAttributeMaxDynamicSharedMemorySize, GEMM_SMEM);
    cudaFuncSetAttribute(gemm3x<1>, cudaFuncAttributeMaxDynamicSharedMemorySize, GEMM_SMEM);

    // 0) mask bias + operand splits
    mask_convert<<<5, 1024>>>(mask);
    split_act<<<(MTOT * DD / 4) / 256, 256>>>(xs, xq);
    split_mat<<<(DD * QKV3 / 4) / 256, 256>>>(qkv_w, g_whi, g_wlo);
    split_mat<<<(DD * DD / 4) / 256, 256>>>(proj_w, g_pwhi, g_pwlo);

    // 1) QKV projection (3xTF32)
    gemm3x<0><<<dim3(QKV3 / 128, MTOT / 128), 256, GEMM_SMEM>>>(g_whi, g_wlo, qkv_b, nullptr);

    // 2) cross attention: Q rows [P, P+N), KV rows [0, 2560)
    attn_tc<<<dim3(NN / 128, HH, BSZ), 256, ATTN_SMEM>>>(PP, ROWS, 0);

    // 3) self attention: Q rows [0, P), KV rows [0, P), scrambled scatter
    attn_tc<<<dim3(PP / 128, HH, BSZ), 256, ATTN_SMEM>>>(0, PP, 1);

    // 4) split attention output, then proj (3xTF32) with tuple scatter
    split_attn<<<(MTOT * DD / 4) / 256, 256>>>();
    gemm3x<1><<<dim3(DD / 128, MTOT / 128), 256, GEMM_SMEM>>>(g_pwhi, g_pwlo, proj_b, out);
}

// round 7
// speedup vs baseline: 1.4252x; 1.4252x over previous
#include <cuda_runtime.h>
#include <cstdint>
#include <cmath>

#define BSZ 2
#define PP 512
#define NN 2048
#define DD 768
#define HH 12
#define HD 64
#define ROWS 2560
#define MTOT 5120
#define QKV3 2304

#define NEG_INF __int_as_float(0xff800000)

// Scratch (__device__ globals: allocation-free rule)
__device__ float g_qkv [(size_t)MTOT * QKV3];     // qkv activations f32
__device__ float g_attn[(size_t)MTOT * DD];       // attention output f32
__device__ uint2 g_actp [(size_t)MTOT * (DD/2)];  // packed bf16 hi/lo pairs, row-major (A operand)
__device__ uint2 g_wqkvp[(size_t)QKV3 * (DD/2)];  // qkv_w transposed+packed [n][k-pairs]
__device__ uint2 g_wprojp[(size_t)DD * (DD/2)];   // proj_w transposed+packed
__device__ float g_mbias[BSZ * ROWS];             // -inf where masked, 0 (padded to 2560)

// ---------------------------------------------------------------------------
// helpers
// ---------------------------------------------------------------------------
__device__ __forceinline__ uint32_t pack2bf(float lo, float hi) {
    uint32_t r;
    asm("cvt.rn.bf16x2.f32 %0, %1, %2;" : "=r"(r) : "f"(hi), "f"(lo));
    return r;
}
// split (x0,x1) -> packed hi pair + packed lo pair
__device__ __forceinline__ void splitpack(float x0, float x1, uint32_t& h, uint32_t& l) {
    h = pack2bf(x0, x1);
    const float h0 = __uint_as_float(h << 16);
    const float h1 = __uint_as_float(h & 0xffff0000u);
    l = pack2bf(x0 - h0, x1 - h1);
}
__device__ __forceinline__ void mma16(float4& d, const uint32_t* a, uint32_t b0, uint32_t b1) {
    asm volatile(
        "mma.sync.aligned.m16n8k16.row.col.f32.bf16.bf16.f32 "
        "{%0,%1,%2,%3},{%4,%5,%6,%7},{%8,%9},{%0,%1,%2,%3};"
        : "+f"(d.x), "+f"(d.y), "+f"(d.z), "+f"(d.w)
        : "r"(a[0]), "r"(a[1]), "r"(a[2]), "r"(a[3]), "r"(b0), "r"(b1));
}

// ---------------------------------------------------------------------------
// Mask: detect dtype (bool8 / int32 / float32), build -inf/0 bias padded to 2560
// ---------------------------------------------------------------------------
__global__ void mask_convert(const uint32_t* __restrict__ mw)
{
    __shared__ int is_bool;
    const int tid = threadIdx.x;
    if (tid == 0) is_bool = 0;
    __syncthreads();
    if (tid < 256) {
        uint32_t w = mw[tid];
        if (w > 1u && w != 0x3F800000u) atomicOr(&is_bool, 1);
    }
    __syncthreads();
    const int i = blockIdx.x * 1024 + tid;
    const int b = i / ROWS, p = i % ROWS;
    float v = 0.0f;
    if (p < PP) {
        const int mi = b * PP + p;
        bool m = is_bool ? (((const uint8_t*)mw)[mi] != 0) : (mw[mi] != 0u);
        v = m ? NEG_INF : 0.0f;
    }
    g_mbias[i] = v;
}

// ---------------------------------------------------------------------------
// Pack activations (virtual concat [xq; xs]) -> g_actp (row-major bf16 hi/lo pairs)
// ---------------------------------------------------------------------------
__global__ void pack_act(const float* __restrict__ xs, const float* __restrict__ xq)
{
    const int i = blockIdx.x * 256 + threadIdx.x;   // over MTOT*192 uint4 entries
    const int row = i / 192, q = i % 192;
    const int b = row / ROWS, r = row % ROWS;
    const float* src = (r < NN) ? xq + ((size_t)b * NN + r) * DD
                                : xs + ((size_t)b * PP + (r - NN)) * DD;
    float4 v = *(const float4*)(src + q * 4);
    uint4 o;
    splitpack(v.x, v.y, o.x, o.y);
    splitpack(v.z, v.w, o.z, o.w);
    ((uint4*)g_actp)[(size_t)row * 192 + q] = o;
}

__global__ void pack_attn()
{
    const int i = blockIdx.x * 256 + threadIdx.x;
    float4 v = *(const float4*)(g_attn + (size_t)i * 4);
    uint4 o;
    splitpack(v.x, v.y, o.x, o.y);
    splitpack(v.z, v.w, o.z, o.w);
    ((uint4*)g_actp)[i] = o;
}

// ---------------------------------------------------------------------------
// Transpose + pack weights: src row-major [768][NB] -> dst [NB][384] uint2
// (k-major pairs per output column), 32x32 smem tiles.
// ---------------------------------------------------------------------------
__global__ void tpack(const float* __restrict__ src, uint2* __restrict__ dst, int NB)
{
    __shared__ float t[32][33];
    const int tid = threadIdx.x;
    const int n0 = blockIdx.x * 32, k0 = blockIdx.y * 32;
#pragma unroll
    for (int s = 0; s < 4; s++) {
        const int r = (tid >> 5) + s * 8, c = tid & 31;
        t[r][c] = src[(size_t)(k0 + r) * NB + n0 + c];
    }
    __syncthreads();
#pragma unroll
    for (int s = 0; s < 2; s++) {
        const int i = (tid >> 4) + s * 16, j = tid & 15;
        uint32_t h, l;
        splitpack(t[2 * j][i], t[2 * j + 1][i], h, l);
        dst[(size_t)(n0 + i) * 384 + k0 / 2 + j] = make_uint2(h, l);
    }
}

// ---------------------------------------------------------------------------
// 3-term bf16 GEMM: C[M x NB] = A[M x 768] @ B[768 x NB] + bias
// A = g_actp (row-major pairs), B = transposed/packed weights.
// 128x128 tile, BK=32, 8 warps (4x2), warp tile 32x64, m16n8k16.
// smem: uint2 arrays, stride 18 (uint4-aligned staging writes).
// EPI 0 -> g_qkv; EPI 1 -> tuple-scatter to output.
// ---------------------------------------------------------------------------
#define GST 18
#define GEMM_SMEM (2 * 128 * GST * 8)

template <int EPI>
__global__ __launch_bounds__(256) void gemm_bf(
    const uint2* __restrict__ Bg, const float* __restrict__ bias, float* __restrict__ Cout)
{
    constexpr int NB = (EPI == 0) ? QKV3 : DD;
    extern __shared__ uint2 sm2[];
    uint2* As2 = sm2;                 // [128][GST]
    uint2* Bs2 = sm2 + 128 * GST;     // [128][GST]

    const int tid = threadIdx.x;
    const int bx = blockIdx.x, by = blockIdx.y;
    const int wid = tid >> 5, lane = tid & 31;
    const int wm = wid >> 1, wn = wid & 1;
    const int lg = lane >> 2, lt = lane & 3;
    const int row0 = by * 128, col0 = bx * 128;

    float4 acc[2][8];
#pragma unroll
    for (int mi = 0; mi < 2; mi++)
#pragma unroll
        for (int ni = 0; ni < 8; ni++) acc[mi][ni] = make_float4(0.f, 0.f, 0.f, 0.f);

    const uint4* Ag4 = (const uint4*)g_actp;
    const uint4* Bg4 = (const uint4*)Bg;
    uint4* As4 = (uint4*)As2;
    uint4* Bs4 = (uint4*)Bs2;

    for (int k0 = 0; k0 < DD; k0 += 32) {
        __syncthreads();
        const int kt = k0 / 4;                     // uint4 offset within row
#pragma unroll
        for (int i = 0; i < 4; i++) {
            const int id = tid + i * 256;          // 1024 entries
            const int r = id >> 3, q = id & 7;
            As4[r * (GST / 2) + q] = Ag4[(size_t)(row0 + r) * 192 + kt + q];
            Bs4[r * (GST / 2) + q] = Bg4[(size_t)(col0 + r) * 192 + kt + q];
        }
        __syncthreads();

#pragma unroll
        for (int ks = 0; ks < 2; ks++) {
            const int kb = ks * 8 + lt;
            uint32_t ah[2][4], al[2][4];
#pragma unroll
            for (int mi = 0; mi < 2; mi++) {
                const int rb = wm * 32 + mi * 16;
                const uint2 A0 = As2[(rb + lg) * GST + kb];
                const uint2 A1 = As2[(rb + 8 + lg) * GST + kb];
                const uint2 A2 = As2[(rb + lg) * GST + kb + 4];
                const uint2 A3 = As2[(rb + 8 + lg) * GST + kb + 4];
                ah[mi][0] = A0.x; ah[mi][1] = A1.x; ah[mi][2] = A2.x; ah[mi][3] = A3.x;
                al[mi][0] = A0.y; al[mi][1] = A1.y; al[mi][2] = A2.y; al[mi][3] = A3.y;
            }
#pragma unroll
            for (int ni = 0; ni < 8; ni++) {
                const int col = wn * 64 + ni * 8 + lg;
                const uint2 B0 = Bs2[col * GST + kb];
                const uint2 B1 = Bs2[col * GST + kb + 4];
#pragma unroll
                for (int mi = 0; mi < 2; mi++) {
                    mma16(acc[mi][ni], ah[mi], B0.x, B1.x);   // hh
                    mma16(acc[mi][ni], ah[mi], B0.y, B1.y);   // hl
                    mma16(acc[mi][ni], al[mi], B0.x, B1.x);   // lh
                }
            }
        }
    }

    // Epilogue
#pragma unroll
    for (int mi = 0; mi < 2; mi++) {
        const int r0 = row0 + wm * 32 + mi * 16 + lg;
#pragma unroll
        for (int ni = 0; ni < 8; ni++) {
            const int col = col0 + wn * 64 + ni * 8 + lt * 2;
            const float b0 = __ldg(&bias[col]), b1 = __ldg(&bias[col + 1]);
            float2 v0 = {acc[mi][ni].x + b0, acc[mi][ni].y + b1};
            float2 v1 = {acc[mi][ni].z + b0, acc[mi][ni].w + b1};
            if (EPI == 0) {
                *(float2*)(g_qkv + (size_t)r0 * NB + col) = v0;
                *(float2*)(g_qkv + (size_t)(r0 + 8) * NB + col) = v1;
            } else {
#pragma unroll
                for (int rr = 0; rr < 2; rr++) {
                    const int g = r0 + rr * 8;
                    const int b = g / ROWS, r = g % ROWS;
                    float* dst = (r < PP)
                        ? Cout + ((size_t)b * PP + r) * DD
                        : Cout + (size_t)BSZ * PP * DD + ((size_t)b * NN + (r - PP)) * DD;
                    *(float2*)(dst + col) = rr ? v1 : v0;
                }
            }
        }
    }
}

// ---------------------------------------------------------------------------
// bf16 3-term flash attention. BQ=128 (8 warps x 16 rows), BKV=64, d=64.
// Q fragments (hi+lo) in registers for the whole KV loop.
// K in smem k-major pairs [kv][d-pair]; V transposed [d][kv-pair].
// P C-layout -> bf16 A-frag via direct pair packing (no shuffles).
// ---------------------------------------------------------------------------
#define QST 34                        // Q/K smem stride (uint2)
#define VSTR 33                       // V smem stride (uint2)
#define ATTN_SMEM (128 * QST * 8 + 512)

__global__ __launch_bounds__(256) void attn_bf(int q_start, int Lk, int self_mode)
{
    extern __shared__ uint2 sm2[];
    uint2* Qs2 = sm2;                            // [128][QST] (staging, then free)
    uint2* Ks2 = sm2;                            // [64][QST]
    uint2* Vs2 = sm2 + 64 * QST;                 // [64][VSTR]
    float* msk = (float*)(sm2 + 64 * QST + 64 * VSTR);   // [64]

    const int tid = threadIdx.x, wid = tid >> 5, lane = tid & 31;
    const int lg = lane >> 2, lt = lane & 3;
    const int h = blockIdx.y, b = blockIdx.z;
    const int q0 = blockIdx.x * 128;
    const size_t rowbase = (size_t)b * ROWS;

    // ---- Stage Q (split+pack) and pull fragments to registers ----
    const float* qg = g_qkv + (rowbase + q_start + q0) * QKV3 + h * HD;
    uint4* Qs4 = (uint4*)Qs2;
#pragma unroll
    for (int i = 0; i < 8; i++) {
        const int id = tid + i * 256;            // 2048 = 128 rows x 16 float4
        const int r = id >> 4, fq = id & 15;
        float4 v = *(const float4*)(qg + (size_t)r * QKV3 + fq * 4);
        uint4 o;
        splitpack(v.x, v.y, o.x, o.y);
        splitpack(v.z, v.w, o.z, o.w);
        Qs4[r * (QST / 2) + fq] = o;
    }
    __syncthreads();
    uint32_t qfh[4][4], qfl[4][4];
    {
        const int qrow = wid * 16 + lg;
#pragma unroll
        for (int kf = 0; kf < 4; kf++) {
            const int kb = kf * 8 + lt;
            const uint2 Q0 = Qs2[qrow * QST + kb];
            const uint2 Q1 = Qs2[(qrow + 8) * QST + kb];
            const uint2 Q2 = Qs2[qrow * QST + kb + 4];
            const uint2 Q3 = Qs2[(qrow + 8) * QST + kb + 4];
            qfh[kf][0] = Q0.x; qfh[kf][1] = Q1.x; qfh[kf][2] = Q2.x; qfh[kf][3] = Q3.x;
            qfl[kf][0] = Q0.y; qfl[kf][1] = Q1.y; qfl[kf][2] = Q2.y; qfl[kf][3] = Q3.y;
        }
    }

    float4 oacc[8];
#pragma unroll
    for (int d = 0; d < 8; d++) oacc[d] = make_float4(0.f, 0.f, 0.f, 0.f);
    float m0 = NEG_INF, m1 = NEG_INF, l0 = 0.f, l1 = 0.f;

    for (int kv0 = 0; kv0 < Lk; kv0 += 64) {
        __syncthreads();
        const float* kg = g_qkv + (rowbase + kv0) * QKV3 + DD + h * HD;
        const float* vg = kg + DD;
        uint4* Ks4 = (uint4*)Ks2;
#pragma unroll
        for (int i = 0; i < 4; i++) {
            const int id = tid + i * 256;        // 1024 = 64 rows x 16 float4
            const int r = id >> 4, fq = id & 15;
            float4 v = *(const float4*)(kg + (size_t)r * QKV3 + fq * 4);
            uint4 o;
            splitpack(v.x, v.y, o.x, o.y);
            splitpack(v.z, v.w, o.z, o.w);
            Ks4[r * (QST / 2) + fq] = o;
        }
        // V transposed: Vs2[d][kvp] = pair over kv
#pragma unroll
        for (int e = 0; e < 8; e++) {
            const int idx = tid + e * 256;       // 2048 = 64 d x 32 kv-pairs
            const int d = idx & 63, kvp = idx >> 6;
            const float f0 = vg[(size_t)(2 * kvp) * QKV3 + d];
            const float f1 = vg[(size_t)(2 * kvp + 1) * QKV3 + d];
            uint32_t hh, ll;
            splitpack(f0, f1, hh, ll);
            Vs2[d * VSTR + kvp] = make_uint2(hh, ll);
        }
        if (tid < 64) msk[tid] = g_mbias[b * ROWS + kv0 + tid];
        __syncthreads();

        // ---- S = Q @ K^T (3-term bf16) ----
        float4 sacc[8];
#pragma unroll
        for (int ni = 0; ni < 8; ni++) sacc[ni] = make_float4(0.f, 0.f, 0.f, 0.f);
#pragma unroll
        for (int kf = 0; kf < 4; kf++) {
            const int kb = kf * 8 + lt;
#pragma unroll
            for (int ni = 0; ni < 8; ni++) {
                const int n = ni * 8 + lg;
                const uint2 K0 = Ks2[n * QST + kb];
                const uint2 K1 = Ks2[n * QST + kb + 4];
                mma16(sacc[ni], qfh[kf], K0.x, K1.x);
                mma16(sacc[ni], qfh[kf], K0.y, K1.y);
                mma16(sacc[ni], qfl[kf], K0.x, K1.x);
            }
        }

        // ---- scale + mask bias, online softmax ----
        float rmax0 = NEG_INF, rmax1 = NEG_INF;
#pragma unroll
        for (int ni = 0; ni < 8; ni++) {
            const float mb0 = msk[ni * 8 + lt * 2];
            const float mb1 = msk[ni * 8 + lt * 2 + 1];
            sacc[ni].x = sacc[ni].x * 0.125f + mb0;
            sacc[ni].y = sacc[ni].y * 0.125f + mb1;
            sacc[ni].z = sacc[ni].z * 0.125f + mb0;
            sacc[ni].w = sacc[ni].w * 0.125f + mb1;
            rmax0 = fmaxf(rmax0, fmaxf(sacc[ni].x, sacc[ni].y));
            rmax1 = fmaxf(rmax1, fmaxf(sacc[ni].z, sacc[ni].w));
        }
        rmax0 = fmaxf(rmax0, __shfl_xor_sync(0xffffffffu, rmax0, 1));
        rmax0 = fmaxf(rmax0, __shfl_xor_sync(0xffffffffu, rmax0, 2));
        rmax1 = fmaxf(rmax1, __shfl_xor_sync(0xffffffffu, rmax1, 1));
        rmax1 = fmaxf(rmax1, __shfl_xor_sync(0xffffffffu, rmax1, 2));

        const float nm0 = fmaxf(m0, rmax0), nm1 = fmaxf(m1, rmax1);
        const float s0 = (nm0 == NEG_INF) ? 0.f : nm0;
        const float s1 = (nm1 == NEG_INF) ? 0.f : nm1;
        const float f0 = __expf(m0 - s0), f1 = __expf(m1 - s1);
        m0 = nm0; m1 = nm1;

        float rs0 = 0.f, rs1 = 0.f;
#pragma unroll
        for (int ni = 0; ni < 8; ni++) {
            sacc[ni].x = __expf(sacc[ni].x - s0);
            sacc[ni].y = __expf(sacc[ni].y - s0);
            sacc[ni].z = __expf(sacc[ni].z - s1);
            sacc[ni].w = __expf(sacc[ni].w - s1);
            rs0 += sacc[ni].x + sacc[ni].y;
            rs1 += sacc[ni].z + sacc[ni].w;
        }
        rs0 += __shfl_xor_sync(0xffffffffu, rs0, 1);
        rs0 += __shfl_xor_sync(0xffffffffu, rs0, 2);
        rs1 += __shfl_xor_sync(0xffffffffu, rs1, 1);
        rs1 += __shfl_xor_sync(0xffffffffu, rs1, 2);
        l0 = l0 * f0 + rs0;
        l1 = l1 * f1 + rs1;
#pragma unroll
        for (int d = 0; d < 8; d++) {
            oacc[d].x *= f0; oacc[d].y *= f0;
            oacc[d].z *= f1; oacc[d].w *= f1;
        }

        // ---- O += P @ V : C-layout pairs pack directly into A-frags ----
#pragma unroll
        for (int g = 0; g < 4; g++) {
            uint32_t pah[4], pal[4];
            splitpack(sacc[2 * g].x,     sacc[2 * g].y,     pah[0], pal[0]);
            splitpack(sacc[2 * g].z,     sacc[2 * g].w,     pah[1], pal[1]);
            splitpack(sacc[2 * g + 1].x, sacc[2 * g + 1].y, pah[2], pal[2]);
            splitpack(sacc[2 * g + 1].z, sacc[2 * g + 1].w, pah[3], pal[3]);
#pragma unroll
            for (int dc = 0; dc < 8; dc++) {
                const int col = dc * 8 + lg;
                const uint2 V0 = Vs2[col * VSTR + g * 8 + lt];
                const uint2 V1 = Vs2[col * VSTR + g * 8 + 4 + lt];
                mma16(oacc[dc], pah, V0.x, V1.x);
                mma16(oacc[dc], pah, V0.y, V1.y);
                mma16(oacc[dc], pal, V0.x, V1.x);
            }
        }
    }

    // ---- finalize ----
    const float inv0 = 1.f / l0, inv1 = 1.f / l1;
    if (!self_mode) {
        const int r0 = q_start + q0 + wid * 16 + lg;
#pragma unroll
        for (int d = 0; d < 8; d++) {
            const int col = h * HD + d * 8 + lt * 2;
            float2 a = {oacc[d].x * inv0, oacc[d].y * inv0};
            float2 c = {oacc[d].z * inv1, oacc[d].w * inv1};
            *(float2*)(g_attn + (rowbase + r0) * DD + col) = a;
            *(float2*)(g_attn + (rowbase + r0 + 8) * DD + col) = c;
        }
    } else {
        const int p0 = q0 + wid * 16 + lg, p1 = p0 + 8;
#pragma unroll
        for (int d = 0; d < 8; d++) {
            const int k = d * 8 + lt * 2;
#pragma unroll
            for (int e = 0; e < 4; e++) {
                const int kk = k + (e & 1);
                const int pp = (e < 2) ? p0 : p1;
                const float val = ((e == 0) ? oacc[d].x * inv0 :
                                   (e == 1) ? oacc[d].y * inv0 :
                                   (e == 2) ? oacc[d].z * inv1 : oacc[d].w * inv1);
                const int f = (h * HD + kk) * PP + pp;
                g_attn[(rowbase + f / DD) * DD + (f % DD)] = val;
            }
        }
    }
}

// ---------------------------------------------------------------------------
extern "C" void kernel_launch(void* const* d_in, const int* in_sizes, int n_in,
                              void* d_out, int out_size)
{
    const float*    xs     = (const float*)d_in[0];
    const float*    xq     = (const float*)d_in[1];
    const uint32_t* mask   = (const uint32_t*)d_in[2];
    const float*    qkv_w  = (const float*)d_in[3];
    const float*    qkv_b  = (const float*)d_in[4];
    const float*    proj_w = (const float*)d_in[5];
    const float*    proj_b = (const float*)d_in[6];
    float*          out    = (float*)d_out;
    (void)in_sizes; (void)n_in; (void)out_size;

    cudaFuncSetAttribute(gemm_bf<0>, cudaFuncAttributeMaxDynamicSharedMemorySize, GEMM_SMEM);
    cudaFuncSetAttribute(gemm_bf<1>, cudaFuncAttributeMaxDynamicSharedMemorySize, GEMM_SMEM);
    cudaFuncSetAttribute(attn_bf, cudaFuncAttributeMaxDynamicSharedMemorySize, ATTN_SMEM);

    // 0) mask + operand packing
    mask_convert<<<5, 1024>>>(mask);
    pack_act<<<(MTOT * 192) / 256, 256>>>(xs, xq);
    tpack<<<dim3(QKV3 / 32, DD / 32), 256>>>(qkv_w, g_wqkvp, QKV3);
    tpack<<<dim3(DD / 32, DD / 32), 256>>>(proj_w, g_wprojp, DD);

    // 1) QKV projection (3-term bf16)
    gemm_bf<0><<<dim3(QKV3 / 128, MTOT / 128), 256, GEMM_SMEM>>>(g_wqkvp, qkv_b, nullptr);

    // 2) cross attention: Q rows [P, P+N), KV rows [0, 2560)
    attn_bf<<<dim3(NN / 128, HH, BSZ), 256, ATTN_SMEM>>>(PP, ROWS, 0);

    // 3) self attention: Q rows [0, P), KV rows [0, P), scrambled scatter
    attn_bf<<<dim3(PP / 128, HH, BSZ), 256, ATTN_SMEM>>>(0, PP, 1);

    // 4) pack attention output, then proj (3-term bf16) + tuple scatter
    pack_attn<<<(MTOT * 192) / 256, 256>>>();
    gemm_bf<1><<<dim3(DD / 128, MTOT / 128), 256, GEMM_SMEM>>>(g_wprojp, proj_b, out);
}

// round 8
// speedup vs baseline: 1.4363x; 1.0077x over previous
#include <cuda_runtime.h>
#include <cstdint>
#include <cmath>

#define BSZ 2
#define PP 512
#define NN 2048
#define DD 768
#define HH 12
#define HD 64
#define ROWS 2560
#define MTOT 5120
#define QKV3 2304

#define NEG_INF __int_as_float(0xff800000)

// Scratch (__device__ globals: allocation-free rule)
__device__ float g_qkv [(size_t)MTOT * QKV3];     // qkv activations f32
__device__ float g_attn[(size_t)MTOT * DD];       // attention output f32
__device__ uint2 g_actp [(size_t)MTOT * (DD/2)];  // packed bf16 hi/lo pairs, row-major (A operand)
__device__ uint2 g_wqkvp[(size_t)QKV3 * (DD/2)];  // qkv_w transposed+packed [n][k-pairs]
__device__ uint2 g_wprojp[(size_t)DD * (DD/2)];   // proj_w transposed+packed
__device__ float g_mbias[BSZ * ROWS];             // -inf where masked, 0 (padded to 2560)

// ---------------------------------------------------------------------------
// helpers
// ---------------------------------------------------------------------------
__device__ __forceinline__ uint32_t pack2bf(float lo, float hi) {
    uint32_t r;
    asm("cvt.rn.bf16x2.f32 %0, %1, %2;" : "=r"(r) : "f"(hi), "f"(lo));
    return r;
}
// split (x0,x1) -> packed hi pair + packed lo pair
__device__ __forceinline__ void splitpack(float x0, float x1, uint32_t& h, uint32_t& l) {
    h = pack2bf(x0, x1);
    const float h0 = __uint_as_float(h << 16);
    const float h1 = __uint_as_float(h & 0xffff0000u);
    l = pack2bf(x0 - h0, x1 - h1);
}
__device__ __forceinline__ void mma16(float4& d, const uint32_t* a, uint32_t b0, uint32_t b1) {
    asm volatile(
        "mma.sync.aligned.m16n8k16.row.col.f32.bf16.bf16.f32 "
        "{%0,%1,%2,%3},{%4,%5,%6,%7},{%8,%9},{%0,%1,%2,%3};"
        : "+f"(d.x), "+f"(d.y), "+f"(d.z), "+f"(d.w)
        : "r"(a[0]), "r"(a[1]), "r"(a[2]), "r"(a[3]), "r"(b0), "r"(b1));
}

// ---------------------------------------------------------------------------
// Mask: detect dtype (bool8 / int32 / float32), build -inf/0 bias padded to 2560
// ---------------------------------------------------------------------------
__global__ void mask_convert(const uint32_t* __restrict__ mw)
{
    __shared__ int is_bool;
    const int tid = threadIdx.x;
    if (tid == 0) is_bool = 0;
    __syncthreads();
    if (tid < 256) {
        uint32_t w = mw[tid];
        if (w > 1u && w != 0x3F800000u) atomicOr(&is_bool, 1);
    }
    __syncthreads();
    const int i = blockIdx.x * 1024 + tid;
    const int b = i / ROWS, p = i % ROWS;
    float v = 0.0f;
    if (p < PP) {
        const int mi = b * PP + p;
        bool m = is_bool ? (((const uint8_t*)mw)[mi] != 0) : (mw[mi] != 0u);
        v = m ? NEG_INF : 0.0f;
    }
    g_mbias[i] = v;
}

// ---------------------------------------------------------------------------
// Pack activations (virtual concat [xq; xs]) -> g_actp (row-major bf16 hi/lo pairs)
// ---------------------------------------------------------------------------
__global__ void pack_act(const float* __restrict__ xs, const float* __restrict__ xq)
{
    const int i = blockIdx.x * 256 + threadIdx.x;   // over MTOT*192 uint4 entries
    const int row = i / 192, q = i % 192;
    const int b = row / ROWS, r = row % ROWS;
    const float* src = (r < NN) ? xq + ((size_t)b * NN + r) * DD
                                : xs + ((size_t)b * PP + (r - NN)) * DD;
    float4 v = *(const float4*)(src + q * 4);
    uint4 o;
    splitpack(v.x, v.y, o.x, o.y);
    splitpack(v.z, v.w, o.z, o.w);
    ((uint4*)g_actp)[(size_t)row * 192 + q] = o;
}

__global__ void pack_attn()
{
    const int i = blockIdx.x * 256 + threadIdx.x;
    float4 v = *(const float4*)(g_attn + (size_t)i * 4);
    uint4 o;
    splitpack(v.x, v.y, o.x, o.y);
    splitpack(v.z, v.w, o.z, o.w);
    ((uint4*)g_actp)[i] = o;
}

// ---------------------------------------------------------------------------
// Transpose + pack weights: src row-major [768][NB] -> dst [NB][384] uint2
// (k-major pairs per output column), 32x32 smem tiles.
// ---------------------------------------------------------------------------
__global__ void tpack(const float* __restrict__ src, uint2* __restrict__ dst, int NB)
{
    __shared__ float t[32][33];
    const int tid = threadIdx.x;
    const int n0 = blockIdx.x * 32, k0 = blockIdx.y * 32;
#pragma unroll
    for (int s = 0; s < 4; s++) {
        const int r = (tid >> 5) + s * 8, c = tid & 31;
        t[r][c] = src[(size_t)(k0 + r) * NB + n0 + c];
    }
    __syncthreads();
#pragma unroll
    for (int s = 0; s < 2; s++) {
        const int i = (tid >> 4) + s * 16, j = tid & 15;
        uint32_t h, l;
        splitpack(t[2 * j][i], t[2 * j + 1][i], h, l);
        dst[(size_t)(n0 + i) * 384 + k0 / 2 + j] = make_uint2(h, l);
    }
}

// ---------------------------------------------------------------------------
// 3-term bf16 GEMM: C[M x NB] = A[M x 768] @ B[768 x NB] + bias
// A = g_actp (row-major pairs), B = transposed/packed weights.
// 128x128 tile, BK=32, 8 warps (4x2), warp tile 32x64, m16n8k16.
// smem: uint2 arrays, stride 18 (uint4-aligned staging writes).
// EPI 0 -> g_qkv; EPI 1 -> tuple-scatter to output.
// ---------------------------------------------------------------------------
#define GST 18
#define GEMM_SMEM (2 * 128 * GST * 8)

template <int EPI>
__global__ __launch_bounds__(256) void gemm_bf(
    const uint2* __restrict__ Bg, const float* __restrict__ bias, float* __restrict__ Cout)
{
    constexpr int NB = (EPI == 0) ? QKV3 : DD;
    extern __shared__ uint2 sm2[];
    uint2* As2 = sm2;                 // [128][GST]
    uint2* Bs2 = sm2 + 128 * GST;     // [128][GST]

    const int tid = threadIdx.x;
    const int bx = blockIdx.x, by = blockIdx.y;
    const int wid = tid >> 5, lane = tid & 31;
    const int wm = wid >> 1, wn = wid & 1;
    const int lg = lane >> 2, lt = lane & 3;
    const int row0 = by * 128, col0 = bx * 128;

    float4 acc[2][8];
#pragma unroll
    for (int mi = 0; mi < 2; mi++)
#pragma unroll
        for (int ni = 0; ni < 8; ni++) acc[mi][ni] = make_float4(0.f, 0.f, 0.f, 0.f);

    const uint4* Ag4 = (const uint4*)g_actp;
    const uint4* Bg4 = (const uint4*)Bg;
    uint4* As4 = (uint4*)As2;
    uint4* Bs4 = (uint4*)Bs2;

    for (int k0 = 0; k0 < DD; k0 += 32) {
        __syncthreads();
        const int kt = k0 / 4;                     // uint4 offset within row
#pragma unroll
        for (int i = 0; i < 4; i++) {
            const int id = tid + i * 256;          // 1024 entries
            const int r = id >> 3, q = id & 7;
            As4[r * (GST / 2) + q] = Ag4[(size_t)(row0 + r) * 192 + kt + q];
            Bs4[r * (GST / 2) + q] = Bg4[(size_t)(col0 + r) * 192 + kt + q];
        }
        __syncthreads();

#pragma unroll
        for (int ks = 0; ks < 2; ks++) {
            const int kb = ks * 8 + lt;
            uint32_t ah[2][4], al[2][4];
#pragma unroll
            for (int mi = 0; mi < 2; mi++) {
                const int rb = wm * 32 + mi * 16;
                const uint2 A0 = As2[(rb + lg) * GST + kb];
                const uint2 A1 = As2[(rb + 8 + lg) * GST + kb];
                const uint2 A2 = As2[(rb + lg) * GST + kb + 4];
                const uint2 A3 = As2[(rb + 8 + lg) * GST + kb + 4];
                ah[mi][0] = A0.x; ah[mi][1] = A1.x; ah[mi][2] = A2.x; ah[mi][3] = A3.x;
                al[mi][0] = A0.y; al[mi][1] = A1.y; al[mi][2] = A2.y; al[mi][3] = A3.y;
            }
#pragma unroll
            for (int ni = 0; ni < 8; ni++) {
                const int col = wn * 64 + ni * 8 + lg;
                const uint2 B0 = Bs2[col * GST + kb];
                const uint2 B1 = Bs2[col * GST + kb + 4];
#pragma unroll
                for (int mi = 0; mi < 2; mi++) {
                    mma16(acc[mi][ni], ah[mi], B0.x, B1.x);   // hh
                    mma16(acc[mi][ni], ah[mi], B0.y, B1.y);   // hl
                    mma16(acc[mi][ni], al[mi], B0.x, B1.x);   // lh
                }
            }
        }
    }

    // Epilogue
#pragma unroll
    for (int mi = 0; mi < 2; mi++) {
        const int r0 = row0 + wm * 32 + mi * 16 + lg;
#pragma unroll
        for (int ni = 0; ni < 8; ni++) {
            const int col = col0 + wn * 64 + ni * 8 + lt * 2;
            const float b0 = __ldg(&bias[col]), b1 = __ldg(&bias[col + 1]);
            float2 v0 = {acc[mi][ni].x + b0, acc[mi][ni].y + b1};
            float2 v1 = {acc[mi][ni].z + b0, acc[mi][ni].w + b1};
            if (EPI == 0) {
                *(float2*)(g_qkv + (size_t)r0 * NB + col) = v0;
                *(float2*)(g_qkv + (size_t)(r0 + 8) * NB + col) = v1;
            } else {
#pragma unroll
                for (int rr = 0; rr < 2; rr++) {
                    const int g = r0 + rr * 8;
                    const int b = g / ROWS, r = g % ROWS;
                    float* dst = (r < PP)
                        ? Cout + ((size_t)b * PP + r) * DD
                        : Cout + (size_t)BSZ * PP * DD + ((size_t)b * NN + (r - PP)) * DD;
                    *(float2*)(dst + col) = rr ? v1 : v0;
                }
            }
        }
    }
}

// ---------------------------------------------------------------------------
// bf16 3-term flash attention. BQ=128 (8 warps x 16 rows), BKV=64, d=64.
// Q fragments (hi+lo) in registers for the whole KV loop.
// K in smem k-major pairs [kv][d-pair]; V transposed [d][kv-pair].
// P C-layout -> bf16 A-frag via direct pair packing (no shuffles).
// ---------------------------------------------------------------------------
#define QST 34                        // Q/K smem stride (uint2)
#define VSTR 33                       // V smem stride (uint2)
#define ATTN_SMEM (128 * QST * 8 + 512)

__global__ __launch_bounds__(256) void attn_bf(int q_start, int Lk, int self_mode)
{
    extern __shared__ uint2 sm2[];
    uint2* Qs2 = sm2;                            // [128][QST] (staging, then free)
    uint2* Ks2 = sm2;                            // [64][QST]
    uint2* Vs2 = sm2 + 64 * QST;                 // [64][VSTR]
    float* msk = (float*)(sm2 + 64 * QST + 64 * VSTR);   // [64]

    const int tid = threadIdx.x, wid = tid >> 5, lane = tid & 31;
    const int lg = lane >> 2, lt = lane & 3;
    const int h = blockIdx.y, b = blockIdx.z;
    const int q0 = blockIdx.x * 128;
    const size_t rowbase = (size_t)b * ROWS;

    // ---- Stage Q (split+pack) and pull fragments to registers ----
    const float* qg = g_qkv + (rowbase + q_start + q0) * QKV3 + h * HD;
    uint4* Qs4 = (uint4*)Qs2;
#pragma unroll
    for (int i = 0; i < 8; i++) {
        const int id = tid + i * 256;            // 2048 = 128 rows x 16 float4
        const int r = id >> 4, fq = id & 15;
        float4 v = *(const float4*)(qg + (size_t)r * QKV3 + fq * 4);
        uint4 o;
        splitpack(v.x, v.y, o.x, o.y);
        splitpack(v.z, v.w, o.z, o.w);
        Qs4[r * (QST / 2) + fq] = o;
    }
    __syncthreads();
    uint32_t qfh[4][4], qfl[4][4];
    {
        const int qrow = wid * 16 + lg;
#pragma unroll
        for (int kf = 0; kf < 4; kf++) {
            const int kb = kf * 8 + lt;
            const uint2 Q0 = Qs2[qrow * QST + kb];
            const uint2 Q1 = Qs2[(qrow + 8) * QST + kb];
            const uint2 Q2 = Qs2[qrow * QST + kb + 4];
            const uint2 Q3 = Qs2[(qrow + 8) * QST + kb + 4];
            qfh[kf][0] = Q0.x; qfh[kf][1] = Q1.x; qfh[kf][2] = Q2.x; qfh[kf][3] = Q3.x;
            qfl[kf][0] = Q0.y; qfl[kf][1] = Q1.y; qfl[kf][2] = Q2.y; qfl[kf][3] = Q3.y;
        }
    }

    float4 oacc[8];
#pragma unroll
    for (int d = 0; d < 8; d++) oacc[d] = make_float4(0.f, 0.f, 0.f, 0.f);
    float m0 = NEG_INF, m1 = NEG_INF, l0 = 0.f, l1 = 0.f;

    for (int kv0 = 0; kv0 < Lk; kv0 += 64) {
        __syncthreads();
        const float* kg = g_qkv + (rowbase + kv0) * QKV3 + DD + h * HD;
        const float* vg = kg + DD;
        uint4* Ks4 = (uint4*)Ks2;
#pragma unroll
        for (int i = 0; i < 4; i++) {
            const int id = tid + i * 256;        // 1024 = 64 rows x 16 float4
            const int r = id >> 4, fq = id & 15;
            float4 v = *(const float4*)(kg + (size_t)r * QKV3 + fq * 4);
            uint4 o;
            splitpack(v.x, v.y, o.x, o.y);
            splitpack(v.z, v.w, o.z, o.w);
            Ks4[r * (QST / 2) + fq] = o;
        }
        // V transposed: Vs2[d][kvp] = pair over kv
#pragma unroll
        for (int e = 0; e < 8; e++) {
            const int idx = tid + e * 256;       // 2048 = 64 d x 32 kv-pairs
            const int d = idx & 63, kvp = idx >> 6;
            const float f0 = vg[(size_t)(2 * kvp) * QKV3 + d];
            const float f1 = vg[(size_t)(2 * kvp + 1) * QKV3 + d];
            uint32_t hh, ll;
            splitpack(f0, f1, hh, ll);
            Vs2[d * VSTR + kvp] = make_uint2(hh, ll);
        }
        if (tid < 64) msk[tid] = g_mbias[b * ROWS + kv0 + tid];
        __syncthreads();

        // ---- S = Q @ K^T (3-term bf16) ----
        float4 sacc[8];
#pragma unroll
        for (int ni = 0; ni < 8; ni++) sacc[ni] = make_float4(0.f, 0.f, 0.f, 0.f);
#pragma unroll
        for (int kf = 0; kf < 4; kf++) {
            const int kb = kf * 8 + lt;
#pragma unroll
            for (int ni = 0; ni < 8; ni++) {
                const int n = ni * 8 + lg;
                const uint2 K0 = Ks2[n * QST + kb];
                const uint2 K1 = Ks2[n * QST + kb + 4];
                mma16(sacc[ni], qfh[kf], K0.x, K1.x);
                mma16(sacc[ni], qfh[kf], K0.y, K1.y);
                mma16(sacc[ni], qfl[kf], K0.x, K1.x);
            }
        }

        // ---- scale + mask bias, online softmax ----
        float rmax0 = NEG_INF, rmax1 = NEG_INF;
#pragma unroll
        for (int ni = 0; ni < 8; ni++) {
            const float mb0 = msk[ni * 8 + lt * 2];
            const float mb1 = msk[ni * 8 + lt * 2 + 1];
            sacc[ni].x = sacc[ni].x * 0.125f + mb0;
            sacc[ni].y = sacc[ni].y * 0.125f + mb1;
            sacc[ni].z = sacc[ni].z * 0.125f + mb0;
            sacc[ni].w = sacc[ni].w * 0.125f + mb1;
            rmax0 = fmaxf(rmax0, fmaxf(sacc[ni].x, sacc[ni].y));
            rmax1 = fmaxf(rmax1, fmaxf(sacc[ni].z, sacc[ni].w));
        }
        rmax0 = fmaxf(rmax0, __shfl_xor_sync(0xffffffffu, rmax0, 1));
        rmax0 = fmaxf(rmax0, __shfl_xor_sync(0xffffffffu, rmax0, 2));
        rmax1 = fmaxf(rmax1, __shfl_xor_sync(0xffffffffu, rmax1, 1));
        rmax1 = fmaxf(rmax1, __shfl_xor_sync(0xffffffffu, rmax1, 2));

        const float nm0 = fmaxf(m0, rmax0), nm1 = fmaxf(m1, rmax1);
        const float s0 = (nm0 == NEG_INF) ? 0.f : nm0;
        const float s1 = (nm1 == NEG_INF) ? 0.f : nm1;
        const float f0 = __expf(m0 - s0), f1 = __expf(m1 - s1);
        m0 = nm0; m1 = nm1;

        float rs0 = 0.f, rs1 = 0.f;
#pragma unroll
        for (int ni = 0; ni < 8; ni++) {
            sacc[ni].x = __expf(sacc[ni].x - s0);
            sacc[ni].y = __expf(sacc[ni].y - s0);
            sacc[ni].z = __expf(sacc[ni].z - s1);
            sacc[ni].w = __expf(sacc[ni].w - s1);
            rs0 += sacc[ni].x + sacc[ni].y;
            rs1 += sacc[ni].z + sacc[ni].w;
        }
        rs0 += __shfl_xor_sync(0xffffffffu, rs0, 1);
        rs0 += __shfl_xor_sync(0xffffffffu, rs0, 2);
        rs1 += __shfl_xor_sync(0xffffffffu, rs1, 1);
        rs1 += __shfl_xor_sync(0xffffffffu, rs1, 2);
        l0 = l0 * f0 + rs0;
        l1 = l1 * f1 + rs1;
#pragma unroll
        for (int d = 0; d < 8; d++) {
            oacc[d].x *= f0; oacc[d].y *= f0;
            oacc[d].z *= f1; oacc[d].w *= f1;
        }

        // ---- O += P @ V : C-layout pairs pack directly into A-frags ----
#pragma unroll
        for (int g = 0; g < 4; g++) {
            uint32_t pah[4], pal[4];
            splitpack(sacc[2 * g].x,     sacc[2 * g].y,     pah[0], pal[0]);
            splitpack(sacc[2 * g].z,     sacc[2 * g].w,     pah[1], pal[1]);
            splitpack(sacc[2 * g + 1].x, sacc[2 * g + 1].y, pah[2], pal[2]);
            splitpack(sacc[2 * g + 1].z, sacc[2 * g + 1].w, pah[3], pal[3]);
#pragma unroll
            for (int dc = 0; dc < 8; dc++) {
                const int col = dc * 8 + lg;
                const uint2 V0 = Vs2[col * VSTR + g * 8 + lt];
                const uint2 V1 = Vs2[col * VSTR + g * 8 + 4 + lt];
                mma16(oacc[dc], pah, V0.x, V1.x);
                mma16(oacc[dc], pah, V0.y, V1.y);
                mma16(oacc[dc], pal, V0.x, V1.x);
            }
        }
    }

    // ---- finalize ----
    const float inv0 = 1.f / l0, inv1 = 1.f / l1;
    if (!self_mode) {
        const int r0 = q_start + q0 + wid * 16 + lg;
#pragma unroll
        for (int d = 0; d < 8; d++) {
            const int col = h * HD + d * 8 + lt * 2;
            float2 a = {oacc[d].x * inv0, oacc[d].y * inv0};
            float2 c = {oacc[d].z * inv1, oacc[d].w * inv1};
            *(float2*)(g_attn + (rowbase + r0) * DD + col) = a;
            *(float2*)(g_attn + (rowbase + r0 + 8) * DD + col) = c;
        }
    } else {
        const int p0 = q0 + wid * 16 + lg, p1 = p0 + 8;
#pragma unroll
        for (int d = 0; d < 8; d++) {
            const int k = d * 8 + lt * 2;
#pragma unroll
            for (int e = 0; e < 4; e++) {
                const int kk = k + (e & 1);
                const int pp = (e < 2) ? p0 : p1;
                const float val = ((e == 0) ? oacc[d].x * inv0 :
                                   (e == 1) ? oacc[d].y * inv0 :
                                   (e == 2) ? oacc[d].z * inv1 : oacc[d].w * inv1);
                const int f = (h * HD + kk) * PP + pp;
                g_attn[(rowbase + f / DD) * DD + (f % DD)] = val;
            }
        }
    }
}

// ---------------------------------------------------------------------------
extern "C" void kernel_launch(void* const* d_in, const int* in_sizes, int n_in,
                              void* d_out, int out_size)
{
    const float*    xs     = (const float*)d_in[0];
    const float*    xq     = (const float*)d_in[1];
    const uint32_t* mask   = (const uint32_t*)d_in[2];
    const float*    qkv_w  = (const float*)d_in[3];
    const float*    qkv_b  = (const float*)d_in[4];
    const float*    proj_w = (const float*)d_in[5];
    const float*    proj_b = (const float*)d_in[6];
    float*          out    = (float*)d_out;
    (void)in_sizes; (void)n_in; (void)out_size;

    cudaFuncSetAttribute(gemm_bf<0>, cudaFuncAttributeMaxDynamicSharedMemorySize, GEMM_SMEM);
    cudaFuncSetAttribute(gemm_bf<1>, cudaFuncAttributeMaxDynamicSharedMemorySize, GEMM_SMEM);
    cudaFuncSetAttribute(attn_bf, cudaFuncAttributeMaxDynamicSharedMemorySize, ATTN_SMEM);

    // 0) mask + operand packing
    mask_convert<<<5, 1024>>>(mask);
    pack_act<<<(MTOT * 192) / 256, 256>>>(xs, xq);
    tpack<<<dim3(QKV3 / 32, DD / 32), 256>>>(qkv_w, g_wqkvp, QKV3);
    tpack<<<dim3(DD / 32, DD / 32), 256>>>(proj_w, g_wprojp, DD);

    // 1) QKV projection (3-term bf16)
    gemm_bf<0><<<dim3(QKV3 / 128, MTOT / 128), 256, GEMM_SMEM>>>(g_wqkvp, qkv_b, nullptr);

    // 2) cross attention: Q rows [P, P+N), KV rows [0, 2560)
    attn_bf<<<dim3(NN / 128, HH, BSZ), 256, ATTN_SMEM>>>(PP, ROWS, 0);

    // 3) self attention: Q rows [0, P), KV rows [0, P), scrambled scatter
    attn_bf<<<dim3(PP / 128, HH, BSZ), 256, ATTN_SMEM>>>(0, PP, 1);

    // 4) pack attention output, then proj (3-term bf16) + tuple scatter
    pack_attn<<<(MTOT * 192) / 256, 256>>>();
    gemm_bf<1><<<dim3(DD / 128, MTOT / 128), 256, GEMM_SMEM>>>(g_wprojp, proj_b, out);
}